// round 10
// baseline (speedup 1.0000x reference)
#include <cuda_runtime.h>
#include <cuda_fp16.h>
#include <cstdint>

// ---------------------------------------------------------------------------
// SparseMoE_2250562863537 (fixed shapes):
//   B=8192, inp = concat(x,y) => D=2048, 8 experts, K=1 top-k
//   K=1 => softmax(single logit)==1 => out[b] = We[e_b] @ inp[b] + be[e_b]
//
// sm_103 (no 'a') => legacy mma.sync only. fp16 single pass (rel err ~3e-4,
// validated R8/R9). R10: CTA tile 128x256, warp tile 64x64 -> smem bytes/MMA
// drop 192->128 (smem crossbar was co-limiting with MMA issue).
// ---------------------------------------------------------------------------
#define B_TOK   8192
#define L_DIM   1024
#define D_DIM   2048
#define N_EXP   8

#define BM      128
#define BN      256
#define BK      64
#define NKIT    (D_DIM / BK)       // 32
#define THREADS 256                // 8 warps: 2(m) x 4(n), warp tile 64x64
#define STAGES  4

// Scratch (device globals — allocation is forbidden)
__device__ int g_cnt[N_EXP];
__device__ int g_list[N_EXP * B_TOK];
__device__ __half g_Ah[B_TOK * D_DIM];                      // 32 MB
__device__ __half g_Wh[(size_t)N_EXP * D_DIM * D_DIM];      // 64 MB (L2-resident)

// ---------------------------------------------------------------------------
// SMEM: header + STAGES x 48KB stages; each stage A(16KB)|B(32KB),
// f16 tiles [rows][64 cols], 128B rows, SW128 xor swizzle
// ---------------------------------------------------------------------------
#define SM_ROWS    0
#define SM_BIAS    512
#define SM_TILES   2048
#define BUF_BYTES  49152
#define OFF_A      0
#define OFF_B      16384
#define SMEM_TOTAL (SM_TILES + STAGES * BUF_BYTES)   // 198656

#define SWZ(b) ((b) ^ (((b) >> 3) & 0x70))

// ---------------------------------------------------------------------------
// helpers
// ---------------------------------------------------------------------------
__device__ __forceinline__ uint32_t smem_u32(const void* p) {
    uint32_t a;
    asm("{ .reg .u64 t; cvta.to.shared.u64 t, %1; cvt.u32.u64 %0, t; }"
        : "=r"(a) : "l"(p));
    return a;
}

#define CP_ASYNC16(dst, src) \
    asm volatile("cp.async.cg.shared.global [%0], [%1], 16;" \
                 :: "r"(dst), "l"(src) : "memory")
#define CP_COMMIT() asm volatile("cp.async.commit_group;" ::: "memory")
#define CP_WAIT(n)  asm volatile("cp.async.wait_group %0;" :: "n"(n) : "memory")

__device__ __forceinline__ void ldsm4(uint32_t* r, uint32_t addr) {
    asm volatile("ldmatrix.sync.aligned.m8n8.x4.shared.b16 {%0,%1,%2,%3}, [%4];"
                 : "=r"(r[0]), "=r"(r[1]), "=r"(r[2]), "=r"(r[3]) : "r"(addr));
}

__device__ __forceinline__ void mma_f16(float* c, const uint32_t* a,
                                        uint32_t b0, uint32_t b1) {
    asm volatile("mma.sync.aligned.m16n8k16.row.col.f32.f16.f16.f32 "
                 "{%0,%1,%2,%3}, {%4,%5,%6,%7}, {%8,%9}, {%0,%1,%2,%3};"
                 : "+f"(c[0]), "+f"(c[1]), "+f"(c[2]), "+f"(c[3])
                 : "r"(a[0]), "r"(a[1]), "r"(a[2]), "r"(a[3]),
                   "r"(b0), "r"(b1));
}

// ---------------------------------------------------------------------------
// Kernel 1: cast We -> g_Wh (f16); block 0 also zeros g_cnt
// ---------------------------------------------------------------------------
__global__ __launch_bounds__(256)
void prep_w_h(const float* __restrict__ We) {
    if (blockIdx.x == 0 && threadIdx.x < N_EXP) g_cnt[threadIdx.x] = 0;
    size_t f = (size_t)blockIdx.x * blockDim.x + threadIdx.x;  // float4 id
    if (f >= (size_t)N_EXP * D_DIM * D_DIM / 4) return;
    float4 v = *reinterpret_cast<const float4*>(We + f * 4);
    *reinterpret_cast<__half2*>(g_Wh + f * 4)     = __floats2half2_rn(v.x, v.y);
    *reinterpret_cast<__half2*>(g_Wh + f * 4 + 2) = __floats2half2_rn(v.z, v.w);
}

// ---------------------------------------------------------------------------
// Kernel 2: FUSED gate + input f16 cast. One warp per token.
// ---------------------------------------------------------------------------
__global__ __launch_bounds__(256)
void gate_prep_fused(const float* __restrict__ x, const float* __restrict__ y,
                     const float* __restrict__ gW, const float* __restrict__ gb) {
    int tok  = blockIdx.x * 8 + (threadIdx.x >> 5);
    int lane = threadIdx.x & 31;

    float acc[N_EXP];
#pragma unroll
    for (int e = 0; e < N_EXP; e++) acc[e] = 0.0f;

#pragma unroll 4
    for (int i = 0; i < 16; i++) {
        int c4  = i * 32 + lane;
        int col = c4 * 4;
        const float* src = (col < L_DIM)
            ? (x + (size_t)tok * L_DIM + col)
            : (y + (size_t)tok * L_DIM + (col - L_DIM));
        float4 v = *reinterpret_cast<const float4*>(src);
        size_t o = (size_t)tok * D_DIM + col;
        *reinterpret_cast<__half2*>(g_Ah + o)     = __floats2half2_rn(v.x, v.y);
        *reinterpret_cast<__half2*>(g_Ah + o + 2) = __floats2half2_rn(v.z, v.w);
#pragma unroll
        for (int e = 0; e < N_EXP; e++) {
            const float4 g = *reinterpret_cast<const float4*>(gW + e * D_DIM + col);
            acc[e] = fmaf(v.x, g.x, fmaf(v.y, g.y, fmaf(v.z, g.z, fmaf(v.w, g.w, acc[e]))));
        }
    }
#pragma unroll
    for (int e = 0; e < N_EXP; e++) {
#pragma unroll
        for (int o = 16; o > 0; o >>= 1)
            acc[e] += __shfl_xor_sync(0xFFFFFFFFu, acc[e], o);
    }
    if (lane == 0) {
        float best = acc[0] + gb[0];
        int   bidx = 0;
#pragma unroll
        for (int e = 1; e < N_EXP; e++) {
            float v = acc[e] + gb[e];
            if (v > best) { best = v; bidx = e; }
        }
        int pos = atomicAdd(&g_cnt[bidx], 1);
        g_list[bidx * B_TOK + pos] = tok;
    }
}

// ---------------------------------------------------------------------------
// Kernel 3: grouped GEMM 128x256, warp tile 64x64, fp16 HMMA, fp32 acc
// ---------------------------------------------------------------------------
__global__ __launch_bounds__(THREADS, 1)
void moe_gemm_h(const float* __restrict__ be, float* __restrict__ out) {
    const int e  = blockIdx.z;
    const int ne = g_cnt[e];
    const int m0 = blockIdx.x * BM;
    if (m0 >= ne) return;
    const int n0 = blockIdx.y * BN;

    extern __shared__ char smem[];
    const uint32_t sbase = smem_u32(smem);
    int*   rs     = (int*)(smem + SM_ROWS);
    float* bias_s = (float*)(smem + SM_BIAS);

    const int tid    = threadIdx.x;
    const int wid    = tid >> 5;
    const int lane   = tid & 31;
    const int warp_m = wid & 1;    // 0..1 -> m offset 0/64
    const int warp_n = wid >> 1;   // 0..3 -> n offset 0/64/128/192

    if (tid < BM) {
        int gm = m0 + tid;
        rs[tid] = (gm < ne) ? g_list[e * B_TOK + gm] : g_list[e * B_TOK];
    }
    if (tid < BN) bias_s[tid] = be[e * D_DIM + n0 + tid];
    __syncthreads();

    // ---- cp.async geometry (recomputed per issue; register-lean) ----
    // chunk: row r = u*32 + (tid>>3), 16B col c = tid&7
    const int      rbase = tid >> 3;                              // 0..31
    const uint32_t coff  = (uint32_t)(tid & 7) * 16;              // bytes
    const uint32_t dst0  = SWZ((uint32_t)rbase * 128 + coff);     // +u*4096 linear
    const char*    bbase = (const char*)(g_Wh +
                           ((size_t)e * D_DIM + n0 + rbase) * D_DIM) + coff;

    auto issue = [&](int kt, int stage) {
        const uint32_t buf = sbase + SM_TILES + stage * BUF_BYTES;
        const size_t kb = (size_t)kt * (BK * 2);   // bytes along K
#pragma unroll
        for (int u = 0; u < 4; u++) {              // A: 128 rows
            int tok = rs[u * 32 + rbase];
            const char* asrc = (const char*)(g_Ah + (size_t)tok * D_DIM) + coff + kb;
            CP_ASYNC16(buf + OFF_A + dst0 + u * 4096, asrc);
        }
#pragma unroll
        for (int u = 0; u < 8; u++) {              // B: 256 rows
            const char* bsrc = bbase + (size_t)u * (32 * D_DIM * 2) + kb;
            CP_ASYNC16(buf + OFF_B + dst0 + u * 4096, bsrc);
        }
        CP_COMMIT();
    };

    // ---- accumulators: 4(m16) x 8(n8) x 4 = 128 regs ----
    float acc[4][8][4];
#pragma unroll
    for (int i = 0; i < 4; i++)
#pragma unroll
        for (int j = 0; j < 8; j++)
#pragma unroll
            for (int c = 0; c < 4; c++) acc[i][j][c] = 0.0f;

    // ldmatrix addressing (128B rows)
    const int lrow = lane & 15;
    const int lsel = lane >> 4;
    uint32_t arow[4], brow[4];
#pragma unroll
    for (int i = 0; i < 4; i++) arow[i] = (uint32_t)((warp_m * 64 + i * 16 + lrow) * 128);
#pragma unroll
    for (int j = 0; j < 4; j++) brow[j] = (uint32_t)((warp_n * 64 + j * 16 + lrow) * 128);
    const uint32_t kbase0 = (uint32_t)(lsel * 16);

    // ---- prologue ----
    issue(0, 0); issue(1, 1); issue(2, 2);

    // ---- mainloop (4-stage rotation) ----
    for (int kt = 0; kt < NKIT; kt++) {
        CP_WAIT(STAGES - 2);
        __syncthreads();
        if (kt + STAGES - 1 < NKIT) issue(kt + STAGES - 1, (kt + STAGES - 1) & 3);

        const uint32_t base = sbase + SM_TILES + (kt & 3) * BUF_BYTES;
        const uint32_t pa = base + OFF_A, pb = base + OFF_B;

#pragma unroll
        for (int ks = 0; ks < 4; ks++) {            // k16 steps within BK=64
            const uint32_t koff = kbase0 + ks * 32;
            uint32_t a[4][4], b[4][4];
#pragma unroll
            for (int i = 0; i < 4; i++) ldsm4(a[i], pa + SWZ(arow[i] + koff));
#pragma unroll
            for (int j = 0; j < 4; j++) ldsm4(b[j], pb + SWZ(brow[j] + koff));
#pragma unroll
            for (int i = 0; i < 4; i++)
#pragma unroll
                for (int j = 0; j < 4; j++) {
#pragma unroll
                    for (int s = 0; s < 2; s++)
                        mma_f16(acc[i][j * 2 + s], a[i], b[j][s], b[j][s + 2]);
                }
        }
    }

    // ---- epilogue: add bias, scatter to token rows ----
    const int gid = lane >> 2;
    const int qid = lane & 3;
#pragma unroll
    for (int i = 0; i < 4; i++) {
#pragma unroll
        for (int h = 0; h < 2; h++) {
            int row = warp_m * 64 + i * 16 + gid + h * 8;
            if (m0 + row < ne) {
                int tok = rs[row];
                float* dst = out + (size_t)tok * D_DIM + n0;
#pragma unroll
                for (int jj = 0; jj < 8; jj++) {
                    int nt = warp_n * 64 + jj * 8 + qid * 2;
                    float2 v;
                    v.x = acc[i][jj][h * 2 + 0] + bias_s[nt + 0];
                    v.y = acc[i][jj][h * 2 + 1] + bias_s[nt + 1];
                    *reinterpret_cast<float2*>(dst + nt) = v;
                }
            }
        }
    }
}

// ---------------------------------------------------------------------------
// Launch
// ---------------------------------------------------------------------------
extern "C" void kernel_launch(void* const* d_in, const int* in_sizes, int n_in,
                              void* d_out, int out_size) {
    const float* x  = (const float*)d_in[0];
    const float* y  = (const float*)d_in[1];
    const float* We = (const float*)d_in[2];
    const float* be = (const float*)d_in[3];
    const float* gW = (const float*)d_in[4];
    const float* gb = (const float*)d_in[5];
    float* out = (float*)d_out;

    cudaFuncSetAttribute(moe_gemm_h,
                         cudaFuncAttributeMaxDynamicSharedMemorySize, SMEM_TOTAL);

    {
        size_t nf4 = (size_t)N_EXP * D_DIM * D_DIM / 4;
        prep_w_h<<<(unsigned)(nf4 / 256), 256>>>(We);      // also zeros g_cnt
    }
    gate_prep_fused<<<B_TOK / 8, 256>>>(x, y, gW, gb);

    dim3 grid(B_TOK / BM, D_DIM / BN, N_EXP);
    moe_gemm_h<<<grid, THREADS, SMEM_TOTAL>>>(be, out);
}

// round 11
// speedup vs baseline: 1.0236x; 1.0236x over previous
#include <cuda_runtime.h>
#include <cuda_fp16.h>
#include <cstdint>

// ---------------------------------------------------------------------------
// SparseMoE_2250562863537 (fixed shapes):
//   B=8192, inp = concat(x,y) => D=2048, 8 experts, K=1 top-k
//   K=1 => softmax(single logit)==1 => out[b] = We[e_b] @ inp[b] + be[e_b]
//
// sm_103 (no 'a') => legacy mma.sync only. fp16 single pass (rel err 3e-4,
// validated R8-R10). R11: CTA 128x128 with 128 THREADS (4 warps, warp tile
// 64x64) at 2 CTAs/SM: smem bytes/MMA drops 192->128 (R9 was smem/MMA
// co-limited) while keeping R9's occupancy. Frags double-buffered across ks.
// ---------------------------------------------------------------------------
#define B_TOK   8192
#define L_DIM   1024
#define D_DIM   2048
#define N_EXP   8

#define BM      128
#define BN      128
#define BK      64
#define NKIT    (D_DIM / BK)       // 32
#define THREADS 128                // 4 warps: 2(m) x 2(n), warp tile 64x64
#define STAGES  3

// Scratch (device globals — allocation is forbidden)
__device__ int g_cnt[N_EXP];
__device__ int g_list[N_EXP * B_TOK];
__device__ __half g_Ah[B_TOK * D_DIM];                      // 32 MB
__device__ __half g_Wh[(size_t)N_EXP * D_DIM * D_DIM];      // 64 MB (L2-resident)

// ---------------------------------------------------------------------------
// SMEM: header + STAGES x 32KB stages; each stage A(16KB)|B(16KB),
// f16 tiles [128 rows][64 cols], 128B rows, SW128 xor swizzle
// ---------------------------------------------------------------------------
#define SM_ROWS    0
#define SM_BIAS    512
#define SM_TILES   1024
#define BUF_BYTES  32768
#define OFF_A      0
#define OFF_B      16384
#define SMEM_TOTAL (SM_TILES + STAGES * BUF_BYTES)   // 99328 -> 2 CTAs/SM

#define SWZ(b) ((b) ^ (((b) >> 3) & 0x70))

// ---------------------------------------------------------------------------
// helpers
// ---------------------------------------------------------------------------
__device__ __forceinline__ uint32_t smem_u32(const void* p) {
    uint32_t a;
    asm("{ .reg .u64 t; cvta.to.shared.u64 t, %1; cvt.u32.u64 %0, t; }"
        : "=r"(a) : "l"(p));
    return a;
}

#define CP_ASYNC16(dst, src) \
    asm volatile("cp.async.cg.shared.global [%0], [%1], 16;" \
                 :: "r"(dst), "l"(src) : "memory")
#define CP_COMMIT() asm volatile("cp.async.commit_group;" ::: "memory")
#define CP_WAIT(n)  asm volatile("cp.async.wait_group %0;" :: "n"(n) : "memory")

__device__ __forceinline__ void ldsm4(uint32_t* r, uint32_t addr) {
    asm volatile("ldmatrix.sync.aligned.m8n8.x4.shared.b16 {%0,%1,%2,%3}, [%4];"
                 : "=r"(r[0]), "=r"(r[1]), "=r"(r[2]), "=r"(r[3]) : "r"(addr));
}

__device__ __forceinline__ void mma_f16(float* c, const uint32_t* a,
                                        uint32_t b0, uint32_t b1) {
    asm volatile("mma.sync.aligned.m16n8k16.row.col.f32.f16.f16.f32 "
                 "{%0,%1,%2,%3}, {%4,%5,%6,%7}, {%8,%9}, {%0,%1,%2,%3};"
                 : "+f"(c[0]), "+f"(c[1]), "+f"(c[2]), "+f"(c[3])
                 : "r"(a[0]), "r"(a[1]), "r"(a[2]), "r"(a[3]),
                   "r"(b0), "r"(b1));
}

// ---------------------------------------------------------------------------
// Kernel 1: cast We -> g_Wh (f16); block 0 also zeros g_cnt
// ---------------------------------------------------------------------------
__global__ __launch_bounds__(256)
void prep_w_h(const float* __restrict__ We) {
    if (blockIdx.x == 0 && threadIdx.x < N_EXP) g_cnt[threadIdx.x] = 0;
    size_t f = (size_t)blockIdx.x * blockDim.x + threadIdx.x;  // float4 id
    if (f >= (size_t)N_EXP * D_DIM * D_DIM / 4) return;
    float4 v = *reinterpret_cast<const float4*>(We + f * 4);
    *reinterpret_cast<__half2*>(g_Wh + f * 4)     = __floats2half2_rn(v.x, v.y);
    *reinterpret_cast<__half2*>(g_Wh + f * 4 + 2) = __floats2half2_rn(v.z, v.w);
}

// ---------------------------------------------------------------------------
// Kernel 2: FUSED gate + input f16 cast. One warp per token.
// ---------------------------------------------------------------------------
__global__ __launch_bounds__(256)
void gate_prep_fused(const float* __restrict__ x, const float* __restrict__ y,
                     const float* __restrict__ gW, const float* __restrict__ gb) {
    int tok  = blockIdx.x * 8 + (threadIdx.x >> 5);
    int lane = threadIdx.x & 31;

    float acc[N_EXP];
#pragma unroll
    for (int e = 0; e < N_EXP; e++) acc[e] = 0.0f;

#pragma unroll 4
    for (int i = 0; i < 16; i++) {
        int c4  = i * 32 + lane;
        int col = c4 * 4;
        const float* src = (col < L_DIM)
            ? (x + (size_t)tok * L_DIM + col)
            : (y + (size_t)tok * L_DIM + (col - L_DIM));
        float4 v = *reinterpret_cast<const float4*>(src);
        size_t o = (size_t)tok * D_DIM + col;
        *reinterpret_cast<__half2*>(g_Ah + o)     = __floats2half2_rn(v.x, v.y);
        *reinterpret_cast<__half2*>(g_Ah + o + 2) = __floats2half2_rn(v.z, v.w);
#pragma unroll
        for (int e = 0; e < N_EXP; e++) {
            const float4 g = *reinterpret_cast<const float4*>(gW + e * D_DIM + col);
            acc[e] = fmaf(v.x, g.x, fmaf(v.y, g.y, fmaf(v.z, g.z, fmaf(v.w, g.w, acc[e]))));
        }
    }
#pragma unroll
    for (int e = 0; e < N_EXP; e++) {
#pragma unroll
        for (int o = 16; o > 0; o >>= 1)
            acc[e] += __shfl_xor_sync(0xFFFFFFFFu, acc[e], o);
    }
    if (lane == 0) {
        float best = acc[0] + gb[0];
        int   bidx = 0;
#pragma unroll
        for (int e = 1; e < N_EXP; e++) {
            float v = acc[e] + gb[e];
            if (v > best) { best = v; bidx = e; }
        }
        int pos = atomicAdd(&g_cnt[bidx], 1);
        g_list[bidx * B_TOK + pos] = tok;
    }
}

// ---------------------------------------------------------------------------
// Kernel 3: grouped GEMM 128x128, 4 warps (64x64 each), fp16 HMMA, fp32 acc
// ---------------------------------------------------------------------------
__global__ __launch_bounds__(THREADS, 2)
void moe_gemm_h(const float* __restrict__ be, float* __restrict__ out) {
    const int e  = blockIdx.z;
    const int ne = g_cnt[e];
    const int m0 = blockIdx.x * BM;
    if (m0 >= ne) return;
    const int n0 = blockIdx.y * BN;

    extern __shared__ char smem[];
    const uint32_t sbase = smem_u32(smem);
    int*   rs     = (int*)(smem + SM_ROWS);
    float* bias_s = (float*)(smem + SM_BIAS);

    const int tid    = threadIdx.x;
    const int wid    = tid >> 5;
    const int lane   = tid & 31;
    const int warp_m = wid & 1;    // m offset 0/64
    const int warp_n = wid >> 1;   // n offset 0/64

    if (tid < BM) {
        int gm = m0 + tid;
        rs[tid]     = (gm < ne) ? g_list[e * B_TOK + gm] : g_list[e * B_TOK];
        bias_s[tid] = be[e * D_DIM + n0 + tid];
    }
    __syncthreads();

    // ---- cp.async geometry: 8 A-chunks + 8 B-chunks per thread ----
    // chunk f = u*128 + tid : row r = f>>3 (0..127), 16B col c = f&7
    const int      rbase = tid >> 3;                              // 0..15
    const uint32_t coff  = (uint32_t)(tid & 7) * 16;
    const uint32_t dst0  = SWZ((uint32_t)rbase * 128 + coff);     // +u*2048 linear
    const char*    bbase = (const char*)(g_Wh +
                           ((size_t)e * D_DIM + n0 + rbase) * D_DIM) + coff;

    auto issue = [&](int kt, int stage) {
        const uint32_t buf = sbase + SM_TILES + stage * BUF_BYTES;
        const size_t kb = (size_t)kt * (BK * 2);   // bytes along K
#pragma unroll
        for (int u = 0; u < 8; u++) {              // A: rows u*16+rbase
            int tok = rs[u * 16 + rbase];
            const char* asrc = (const char*)(g_Ah + (size_t)tok * D_DIM) + coff + kb;
            CP_ASYNC16(buf + OFF_A + dst0 + u * 2048, asrc);
        }
#pragma unroll
        for (int u = 0; u < 8; u++) {              // B: rows u*16+rbase
            const char* bsrc = bbase + (size_t)u * (16 * D_DIM * 2) + kb;
            CP_ASYNC16(buf + OFF_B + dst0 + u * 2048, bsrc);
        }
        CP_COMMIT();
    };

    // ---- accumulators: 4(m16) x 8(n8) x 4 = 128 regs ----
    float acc[4][8][4];
#pragma unroll
    for (int i = 0; i < 4; i++)
#pragma unroll
        for (int j = 0; j < 8; j++)
#pragma unroll
            for (int c = 0; c < 4; c++) acc[i][j][c] = 0.0f;

    // ldmatrix addressing (128B rows)
    const int lrow = lane & 15;
    const int lsel = lane >> 4;
    uint32_t arow[4], brow[4];
#pragma unroll
    for (int i = 0; i < 4; i++) arow[i] = (uint32_t)((warp_m * 64 + i * 16 + lrow) * 128);
#pragma unroll
    for (int j = 0; j < 4; j++) brow[j] = (uint32_t)((warp_n * 64 + j * 16 + lrow) * 128);
    const uint32_t kbase0 = (uint32_t)(lsel * 16);

    // fragment double buffers (a: 16 regs x2, b: 16 regs x2)
    uint32_t afr[2][4][4], bfr[2][4][4];

    auto load_frags = [&](uint32_t pa, uint32_t pb, int ks, int slot) {
        const uint32_t koff = kbase0 + ks * 32;
#pragma unroll
        for (int i = 0; i < 4; i++) ldsm4(afr[slot][i], pa + SWZ(arow[i] + koff));
#pragma unroll
        for (int j = 0; j < 4; j++) ldsm4(bfr[slot][j], pb + SWZ(brow[j] + koff));
    };
    auto do_mmas = [&](int slot) {
#pragma unroll
        for (int i = 0; i < 4; i++)
#pragma unroll
            for (int j = 0; j < 4; j++)
#pragma unroll
                for (int s = 0; s < 2; s++)
                    mma_f16(acc[i][j * 2 + s], afr[slot][i],
                            bfr[slot][j][s], bfr[slot][j][s + 2]);
    };

    // ---- prologue ----
    issue(0, 0); issue(1, 1);

    // ---- mainloop (3-stage smem rotation, 2-slot frag rotation) ----
    int cur = 0, nx = 2;
    for (int kt = 0; kt < NKIT; kt++) {
        CP_WAIT(STAGES - 2);
        __syncthreads();
        if (kt + 2 < NKIT) issue(kt + 2, nx);

        const uint32_t base = sbase + SM_TILES + cur * BUF_BYTES;
        const uint32_t pa = base + OFF_A, pb = base + OFF_B;

        load_frags(pa, pb, 0, 0);
#pragma unroll
        for (int ks = 0; ks < 4; ks++) {
            if (ks < 3) load_frags(pa, pb, ks + 1, (ks + 1) & 1);  // prefetch
            do_mmas(ks & 1);
        }
        if (++cur == STAGES) cur = 0;
        if (++nx  == STAGES) nx  = 0;
    }

    // ---- epilogue: add bias, scatter to token rows ----
    const int gid = lane >> 2;
    const int qid = lane & 3;
#pragma unroll
    for (int i = 0; i < 4; i++) {
#pragma unroll
        for (int h = 0; h < 2; h++) {
            int row = warp_m * 64 + i * 16 + gid + h * 8;
            if (m0 + row < ne) {
                int tok = rs[row];
                float* dst = out + (size_t)tok * D_DIM + n0;
#pragma unroll
                for (int jj = 0; jj < 8; jj++) {
                    int nt = warp_n * 64 + jj * 8 + qid * 2;
                    float2 v;
                    v.x = acc[i][jj][h * 2 + 0] + bias_s[nt + 0];
                    v.y = acc[i][jj][h * 2 + 1] + bias_s[nt + 1];
                    *reinterpret_cast<float2*>(dst + nt) = v;
                }
            }
        }
    }
}

// ---------------------------------------------------------------------------
// Launch
// ---------------------------------------------------------------------------
extern "C" void kernel_launch(void* const* d_in, const int* in_sizes, int n_in,
                              void* d_out, int out_size) {
    const float* x  = (const float*)d_in[0];
    const float* y  = (const float*)d_in[1];
    const float* We = (const float*)d_in[2];
    const float* be = (const float*)d_in[3];
    const float* gW = (const float*)d_in[4];
    const float* gb = (const float*)d_in[5];
    float* out = (float*)d_out;

    cudaFuncSetAttribute(moe_gemm_h,
                         cudaFuncAttributeMaxDynamicSharedMemorySize, SMEM_TOTAL);

    {
        size_t nf4 = (size_t)N_EXP * D_DIM * D_DIM / 4;
        prep_w_h<<<(unsigned)(nf4 / 256), 256>>>(We);      // also zeros g_cnt
    }
    gate_prep_fused<<<B_TOK / 8, 256>>>(x, y, gW, gb);

    dim3 grid(B_TOK / BM, D_DIM / BN, N_EXP);
    moe_gemm_h<<<grid, THREADS, SMEM_TOTAL>>>(be, out);
}

// round 12
// speedup vs baseline: 1.0790x; 1.0541x over previous
#include <cuda_runtime.h>
#include <cuda_fp16.h>
#include <cstdint>

// ---------------------------------------------------------------------------
// SparseMoE_2250562863537 (fixed shapes):
//   B=8192, inp = concat(x,y) => D=2048, 8 experts, K=1 top-k
//   K=1 => softmax(single logit)==1 => out[b] = We[e_b] @ inp[b] + be[e_b]
//
// sm_103 (no 'a') => legacy mma.sync only. fp16 single pass (rel err 3e-4,
// validated R8-R11). R12 = R9 config (BM=BN=128, 8 warps 64x32, STAGES=3,
// 2 CTAs/SM, <=128 regs) + cp.async issue SPREAD across the 4 ks steps:
// kills the post-barrier LDGSTS convoy (rt=8/SMSP) that blocked MMA issue.
// ---------------------------------------------------------------------------
#define B_TOK   8192
#define L_DIM   1024
#define D_DIM   2048
#define N_EXP   8

#define BM      128
#define BN      128
#define BK      64
#define NKIT    (D_DIM / BK)       // 32
#define THREADS 256                // 8 warps: 2(m) x 4(n), warp tile 64x32
#define STAGES  3

// Scratch (device globals — allocation is forbidden)
__device__ int g_cnt[N_EXP];
__device__ int g_list[N_EXP * B_TOK];
__device__ __half g_Ah[B_TOK * D_DIM];                      // 32 MB
__device__ __half g_Wh[(size_t)N_EXP * D_DIM * D_DIM];      // 64 MB (L2-resident)

// ---------------------------------------------------------------------------
// SMEM: header + STAGES x 32KB stages; each stage A(16KB)|B(16KB),
// f16 tiles [128 rows][64 cols], 128B rows, SW128 xor swizzle
// ---------------------------------------------------------------------------
#define SM_ROWS    0
#define SM_BIAS    512
#define SM_TILES   1024
#define BUF_BYTES  32768
#define OFF_A      0
#define OFF_B      16384
#define SMEM_TOTAL (SM_TILES + STAGES * BUF_BYTES)   // 99328 -> 2 CTAs/SM

#define SWZ(b) ((b) ^ (((b) >> 3) & 0x70))

// ---------------------------------------------------------------------------
// helpers
// ---------------------------------------------------------------------------
__device__ __forceinline__ uint32_t smem_u32(const void* p) {
    uint32_t a;
    asm("{ .reg .u64 t; cvta.to.shared.u64 t, %1; cvt.u32.u64 %0, t; }"
        : "=r"(a) : "l"(p));
    return a;
}

#define CP_ASYNC16(dst, src) \
    asm volatile("cp.async.cg.shared.global [%0], [%1], 16;" \
                 :: "r"(dst), "l"(src) : "memory")
#define CP_COMMIT() asm volatile("cp.async.commit_group;" ::: "memory")
#define CP_WAIT(n)  asm volatile("cp.async.wait_group %0;" :: "n"(n) : "memory")

__device__ __forceinline__ void ldsm4(uint32_t* r, uint32_t addr) {
    asm volatile("ldmatrix.sync.aligned.m8n8.x4.shared.b16 {%0,%1,%2,%3}, [%4];"
                 : "=r"(r[0]), "=r"(r[1]), "=r"(r[2]), "=r"(r[3]) : "r"(addr));
}

__device__ __forceinline__ void mma_f16(float* c, const uint32_t* a,
                                        uint32_t b0, uint32_t b1) {
    asm volatile("mma.sync.aligned.m16n8k16.row.col.f32.f16.f16.f32 "
                 "{%0,%1,%2,%3}, {%4,%5,%6,%7}, {%8,%9}, {%0,%1,%2,%3};"
                 : "+f"(c[0]), "+f"(c[1]), "+f"(c[2]), "+f"(c[3])
                 : "r"(a[0]), "r"(a[1]), "r"(a[2]), "r"(a[3]),
                   "r"(b0), "r"(b1));
}

// ---------------------------------------------------------------------------
// Kernel 1: cast We -> g_Wh (f16); block 0 also zeros g_cnt
// ---------------------------------------------------------------------------
__global__ __launch_bounds__(256)
void prep_w_h(const float* __restrict__ We) {
    if (blockIdx.x == 0 && threadIdx.x < N_EXP) g_cnt[threadIdx.x] = 0;
    size_t f = (size_t)blockIdx.x * blockDim.x + threadIdx.x;  // float4 id
    if (f >= (size_t)N_EXP * D_DIM * D_DIM / 4) return;
    float4 v = *reinterpret_cast<const float4*>(We + f * 4);
    *reinterpret_cast<__half2*>(g_Wh + f * 4)     = __floats2half2_rn(v.x, v.y);
    *reinterpret_cast<__half2*>(g_Wh + f * 4 + 2) = __floats2half2_rn(v.z, v.w);
}

// ---------------------------------------------------------------------------
// Kernel 2: FUSED gate + input f16 cast. One warp per token.
// ---------------------------------------------------------------------------
__global__ __launch_bounds__(256)
void gate_prep_fused(const float* __restrict__ x, const float* __restrict__ y,
                     const float* __restrict__ gW, const float* __restrict__ gb) {
    int tok  = blockIdx.x * 8 + (threadIdx.x >> 5);
    int lane = threadIdx.x & 31;

    float acc[N_EXP];
#pragma unroll
    for (int e = 0; e < N_EXP; e++) acc[e] = 0.0f;

#pragma unroll 4
    for (int i = 0; i < 16; i++) {
        int c4  = i * 32 + lane;
        int col = c4 * 4;
        const float* src = (col < L_DIM)
            ? (x + (size_t)tok * L_DIM + col)
            : (y + (size_t)tok * L_DIM + (col - L_DIM));
        float4 v = *reinterpret_cast<const float4*>(src);
        size_t o = (size_t)tok * D_DIM + col;
        *reinterpret_cast<__half2*>(g_Ah + o)     = __floats2half2_rn(v.x, v.y);
        *reinterpret_cast<__half2*>(g_Ah + o + 2) = __floats2half2_rn(v.z, v.w);
#pragma unroll
        for (int e = 0; e < N_EXP; e++) {
            const float4 g = *reinterpret_cast<const float4*>(gW + e * D_DIM + col);
            acc[e] = fmaf(v.x, g.x, fmaf(v.y, g.y, fmaf(v.z, g.z, fmaf(v.w, g.w, acc[e]))));
        }
    }
#pragma unroll
    for (int e = 0; e < N_EXP; e++) {
#pragma unroll
        for (int o = 16; o > 0; o >>= 1)
            acc[e] += __shfl_xor_sync(0xFFFFFFFFu, acc[e], o);
    }
    if (lane == 0) {
        float best = acc[0] + gb[0];
        int   bidx = 0;
#pragma unroll
        for (int e = 1; e < N_EXP; e++) {
            float v = acc[e] + gb[e];
            if (v > best) { best = v; bidx = e; }
        }
        int pos = atomicAdd(&g_cnt[bidx], 1);
        g_list[bidx * B_TOK + pos] = tok;
    }
}

// ---------------------------------------------------------------------------
// Kernel 3: grouped GEMM 128x128, 8 warps (64x32), fp16 HMMA, fp32 acc.
// cp.async issue interleaved into the ks loop (2 LDGSTS/thread per ks).
// ---------------------------------------------------------------------------
__global__ __launch_bounds__(THREADS, 2)
void moe_gemm_h(const float* __restrict__ be, float* __restrict__ out) {
    const int e  = blockIdx.z;
    const int ne = g_cnt[e];
    const int m0 = blockIdx.x * BM;
    if (m0 >= ne) return;
    const int n0 = blockIdx.y * BN;

    extern __shared__ char smem[];
    const uint32_t sbase = smem_u32(smem);
    int*   rs     = (int*)(smem + SM_ROWS);
    float* bias_s = (float*)(smem + SM_BIAS);

    const int tid    = threadIdx.x;
    const int wid    = tid >> 5;
    const int lane   = tid & 31;
    const int warp_m = wid & 1;    // m offset 0/64
    const int warp_n = wid >> 1;   // n offset 0/32/64/96

    if (tid < BM) {
        int gm = m0 + tid;
        rs[tid]     = (gm < ne) ? g_list[e * B_TOK + gm] : g_list[e * B_TOK];
        bias_s[tid] = be[e * D_DIM + n0 + tid];
    }
    __syncthreads();

    // ---- cp.async geometry: chunk f = u*256+tid : row r=f>>3, 16B col c=f&7
    const int      rbase = tid >> 3;                              // 0..31
    const uint32_t coff  = (uint32_t)(tid & 7) * 16;
    const uint32_t dst0  = SWZ((uint32_t)rbase * 128 + coff);     // +u*4096 linear
    const char*    bbase = (const char*)(g_Wh +
                           ((size_t)e * D_DIM + n0 + rbase) * D_DIM) + coff;

    // one A-chunk + one B-chunk (u = part 0..3); called 4x per iteration
    auto issue_part = [&](int kt, int stage, int u) {
        const uint32_t buf = sbase + SM_TILES + stage * BUF_BYTES;
        const size_t kb = (size_t)kt * (BK * 2);
        int tok = rs[u * 32 + rbase];
        const char* asrc = (const char*)(g_Ah + (size_t)tok * D_DIM) + coff + kb;
        const char* bsrc = bbase + (size_t)u * (32 * D_DIM * 2) + kb;
        CP_ASYNC16(buf + OFF_A + dst0 + u * 4096, asrc);
        CP_ASYNC16(buf + OFF_B + dst0 + u * 4096, bsrc);
    };
    auto issue_full = [&](int kt, int stage) {
#pragma unroll
        for (int u = 0; u < 4; u++) issue_part(kt, stage, u);
        CP_COMMIT();
    };

    // ---- accumulators: 4(m16) x 4(n8) x 4 = 64 regs ----
    float acc[4][4][4];
#pragma unroll
    for (int i = 0; i < 4; i++)
#pragma unroll
        for (int j = 0; j < 4; j++)
#pragma unroll
            for (int c = 0; c < 4; c++) acc[i][j][c] = 0.0f;

    // ldmatrix addressing (128B rows)
    const int lrow = lane & 15;
    const int lsel = lane >> 4;
    uint32_t arow[4], brow[2];
#pragma unroll
    for (int i = 0; i < 4; i++) arow[i] = (uint32_t)((warp_m * 64 + i * 16 + lrow) * 128);
#pragma unroll
    for (int j = 0; j < 2; j++) brow[j] = (uint32_t)((warp_n * 32 + j * 16 + lrow) * 128);
    const uint32_t kbase0 = (uint32_t)(lsel * 16);

    // ---- prologue ----
    issue_full(0, 0);
    issue_full(1, 1);

    // ---- mainloop (3-stage rotation; cp.async spread over ks steps) ----
    int cur = 0, nx = 2;
    for (int kt = 0; kt < NKIT; kt++) {
        CP_WAIT(STAGES - 2);
        __syncthreads();

        const bool more = (kt + 2 < NKIT);
        const int  knx  = kt + 2;
        const uint32_t base = sbase + SM_TILES + cur * BUF_BYTES;
        const uint32_t pa = base + OFF_A, pb = base + OFF_B;

#pragma unroll
        for (int ks = 0; ks < 4; ks++) {
            // interleave one quarter of next tile's cp.async with this burst
            if (more) issue_part(knx, nx, ks);

            const uint32_t koff = kbase0 + ks * 32;
            uint32_t a[4][4], b[2][4];
#pragma unroll
            for (int i = 0; i < 4; i++) ldsm4(a[i], pa + SWZ(arow[i] + koff));
#pragma unroll
            for (int j = 0; j < 2; j++) ldsm4(b[j], pb + SWZ(brow[j] + koff));
#pragma unroll
            for (int i = 0; i < 4; i++)
#pragma unroll
                for (int jj = 0; jj < 4; jj++) {
                    const int j = jj >> 1, s = jj & 1;
                    mma_f16(acc[i][jj], a[i], b[j][s], b[j][s + 2]);
                }
        }
        CP_COMMIT();   // one group per iteration (empty on tail iters: ok)

        if (++cur == STAGES) cur = 0;
        if (++nx  == STAGES) nx  = 0;
    }

    // ---- epilogue: add bias, scatter to token rows ----
    const int gid = lane >> 2;
    const int qid = lane & 3;
#pragma unroll
    for (int i = 0; i < 4; i++) {
#pragma unroll
        for (int h = 0; h < 2; h++) {
            int row = warp_m * 64 + i * 16 + gid + h * 8;
            if (m0 + row < ne) {
                int tok = rs[row];
                float* dst = out + (size_t)tok * D_DIM + n0;
#pragma unroll
                for (int jj = 0; jj < 4; jj++) {
                    int nt = warp_n * 32 + jj * 8 + qid * 2;
                    float2 v;
                    v.x = acc[i][jj][h * 2 + 0] + bias_s[nt + 0];
                    v.y = acc[i][jj][h * 2 + 1] + bias_s[nt + 1];
                    *reinterpret_cast<float2*>(dst + nt) = v;
                }
            }
        }
    }
}

// ---------------------------------------------------------------------------
// Launch
// ---------------------------------------------------------------------------
extern "C" void kernel_launch(void* const* d_in, const int* in_sizes, int n_in,
                              void* d_out, int out_size) {
    const float* x  = (const float*)d_in[0];
    const float* y  = (const float*)d_in[1];
    const float* We = (const float*)d_in[2];
    const float* be = (const float*)d_in[3];
    const float* gW = (const float*)d_in[4];
    const float* gb = (const float*)d_in[5];
    float* out = (float*)d_out;

    cudaFuncSetAttribute(moe_gemm_h,
                         cudaFuncAttributeMaxDynamicSharedMemorySize, SMEM_TOTAL);

    {
        size_t nf4 = (size_t)N_EXP * D_DIM * D_DIM / 4;
        prep_w_h<<<(unsigned)(nf4 / 256), 256>>>(We);      // also zeros g_cnt
    }
    gate_prep_fused<<<B_TOK / 8, 256>>>(x, y, gW, gb);

    dim3 grid(B_TOK / BM, D_DIM / BN, N_EXP);
    moe_gemm_h<<<grid, THREADS, SMEM_TOTAL>>>(be, out);
}